// round 5
// baseline (speedup 1.0000x reference)
#include <cuda_runtime.h>
#include <cstdint>

#define IN_CH 16
#define OUT_CH 32
#define BATCH 8
#define H 32
#define W 32
#define NCP (IN_CH / 2)            // 8 channel pairs
#define NTAP 9
#define NPAIRTRIP (NCP * NTAP * OUT_CH)   // 2304 float2 per table

typedef unsigned long long ull;

// Packed coefficient tables: [0..2303]=np1, [2304..4607]=sm, [4608..6911]=dsh
// Each entry: float2 (lo = channel 2cp, hi = channel 2cp+1), index (cp*9+tap)*32+o
__device__ float2 g_coef[3 * NPAIRTRIP];
__device__ float  g_base[OUT_CH];

__device__ __forceinline__ ull add2(ull a, ull b) {
    ull r; asm("add.rn.f32x2 %0, %1, %2;" : "=l"(r) : "l"(a), "l"(b)); return r;
}
__device__ __forceinline__ ull fma2(ull a, ull b, ull c) {
    ull r; asm("fma.rn.f32x2 %0, %1, %2, %3;" : "=l"(r) : "l"(a), "l"(b), "l"(c)); return r;
}

// ---------------------------------------------------------------------------
// Kernel 1: coefficients, once.
//   y_i(x) = v1 + sm*d + dsh*|d|, d = x - p1, sm=(s0+s1)/2, dsh=(s1-s0)/2
// ---------------------------------------------------------------------------
__global__ void coef_kernel(const float* __restrict__ pos,
                            const float* __restrict__ val) {
    if (blockIdx.x < 18) {
        int t = blockIdx.x * 256 + threadIdx.x;    // (i, o), i = c*9+tap
        int o = t & 31;
        int i = t >> 5;
        int c = i / 9, tap = i - c * 9;
        int base = t * 3;
        float p0 = pos[base], p1 = pos[base + 1], p2 = pos[base + 2];
        float v0 = val[base], v1 = val[base + 1], v2 = val[base + 2];
        float s0 = (v1 - v0) / (p1 - p0);
        float s1 = (v2 - v1) / (p2 - p1);
        int idx = ((c >> 1) * 9 + tap) * 32 + o;
        int hf = c & 1;
        ((float*)&g_coef[idx])[hf]                 = -p1;
        ((float*)&g_coef[idx + NPAIRTRIP])[hf]     = 0.5f * (s0 + s1);
        ((float*)&g_coef[idx + 2 * NPAIRTRIP])[hf] = 0.5f * (s1 - s0);
    } else if (threadIdx.x < 32) {
        float s = 0.f;
        #pragma unroll 16
        for (int i = 0; i < 144; i++)
            s += val[(i * 32 + threadIdx.x) * 3 + 1];
        g_base[threadIdx.x] = s;
    }
}

// ---------------------------------------------------------------------------
// Kernel 2: main compute. Block = (image, output row), 256 threads = 8 warps.
//   Warp w owns pixels 4w..4w+3; lane = output channel o.
//   Tile is channel-interleaved (pad 18) so (c,c+1) x-values are one LDS.64.
//   Coefs are channel-pair-packed float2, LDS.64. Zero pack MOVs in the loop.
// ---------------------------------------------------------------------------
#define CH_PAD 18
#define TCOLS 34
#define TILE_FLOATS (3 * TCOLS * CH_PAD)          // 1836
#define OFF_COEF 0                                 // 6912 float2 = 55296 B
#define OFF_TILE 55296                             // 7344 B
#define OFF_OUT  62640                             // [32][33] = 4224 B
#define SMEM_BYTES 66864

__global__ __launch_bounds__(256, 2)
void apc_main(const float* __restrict__ x, float* __restrict__ out) {
    extern __shared__ char sm_raw[];
    ull*   c_np1 = (ull*)(sm_raw + OFF_COEF);
    ull*   c_sm  = c_np1 + NPAIRTRIP;
    ull*   c_dsh = c_np1 + 2 * NPAIRTRIP;
    float* tile  = (float*)(sm_raw + OFF_TILE);
    ull*   tile64 = (ull*)tile;
    float* outst = (float*)(sm_raw + OFF_OUT);

    const int tid = threadIdx.x;
    const int b = blockIdx.x >> 5;
    const int y = blockIdx.x & 31;

    // ---- copy packed coef tables global -> smem (float4, coalesced) ----
    {
        const float4* src = (const float4*)g_coef;
        float4* dst = (float4*)c_np1;
        #pragma unroll
        for (int k = 0; k < 14; k++) {
            int idx = tid + k * 256;
            if (idx < 3 * NPAIRTRIP / 2) dst[idx] = src[idx];
        }
    }

    // ---- stage tile rows y-1..y+1, cols -1..32, interleaved, zero halo ----
    const float* xb = x + b * (IN_CH * H * W);
    for (int idx = tid; idx < 3 * TCOLS * IN_CH; idx += 256) {
        int c   = idx / (3 * TCOLS);          // channel outer: gmem coalesced
        int rem = idx - c * (3 * TCOLS);
        int r   = rem / TCOLS;
        int col = rem - r * TCOLS;
        int gy = y + r - 1;
        int gx = col - 1;
        float v = 0.f;
        if ((unsigned)gy < (unsigned)H && (unsigned)gx < (unsigned)W)
            v = xb[(c * H + gy) * W + gx];
        tile[(r * TCOLS + col) * CH_PAD + c] = v;   // stride-18 STS: deg-2 max
    }
    __syncthreads();

    // ---- main loop ----
    const int w = tid >> 5;          // warp -> pixel group
    const int o = tid & 31;          // lane -> output channel
    const int px0 = w << 2;

    ull accA[4] = {0, 0, 0, 0};
    ull accB[4] = {0, 0, 0, 0};
    const ull ABS2 = 0x7FFFFFFF7FFFFFFFull;

    #pragma unroll 2
    for (int cp = 0; cp < NCP; cp++) {
        // x window: 3 rows x 6 cols of channel-pairs, native LDS.64, broadcast
        ull xw[3][6];
        #pragma unroll
        for (int kh = 0; kh < 3; kh++)
            #pragma unroll
            for (int m = 0; m < 6; m++)
                xw[kh][m] = tile64[(kh * TCOLS + px0 + m) * (CH_PAD / 2) + cp];

        const ull* p1 = c_np1 + cp * (NTAP * 32) + o;
        const ull* p2 = c_sm  + cp * (NTAP * 32) + o;
        const ull* p3 = c_dsh + cp * (NTAP * 32) + o;

        #pragma unroll
        for (int t = 0; t < NTAP; t++) {
            const int kh = t / 3, kw = t % 3;
            const ull np1 = p1[t * 32];     // compile-time immediate offsets
            const ull smv = p2[t * 32];
            const ull dsh = p3[t * 32];
            #pragma unroll
            for (int p = 0; p < 4; p++) {
                ull d = add2(xw[kh][p + kw], np1);
                ull a = d & ABS2;                       // |d| per half: 2x LOP3
                if (t & 1) {
                    accB[p] = fma2(smv, d, accB[p]);
                    accB[p] = fma2(dsh, a, accB[p]);
                } else {
                    accA[p] = fma2(smv, d, accA[p]);
                    accA[p] = fma2(dsh, a, accA[p]);
                }
            }
        }
    }

    // ---- horizontal reduce -> padded smem ----
    #pragma unroll
    for (int p = 0; p < 4; p++) {
        ull s2 = add2(accA[p], accB[p]);
        float lo = __uint_as_float((unsigned)s2);
        float hi = __uint_as_float((unsigned)(s2 >> 32));
        outst[(px0 + p) * 33 + o] = lo + hi;
    }
    __syncthreads();

    // ---- transposed, coalesced store + base ----
    #pragma unroll
    for (int k = 0; k < 4; k++) {
        int q  = tid + k * 256;
        int oo = q >> 5;
        int px = q & 31;
        out[((b * OUT_CH + oo) * H + y) * W + px] =
            outst[px * 33 + oo] + g_base[oo];
    }
}

extern "C" void kernel_launch(void* const* d_in, const int* in_sizes, int n_in,
                              void* d_out, int out_size) {
    const float* x   = (const float*)d_in[0];
    const float* pos = (const float*)d_in[1];
    const float* val = (const float*)d_in[2];
    float* out = (float*)d_out;

    cudaFuncSetAttribute(apc_main, cudaFuncAttributeMaxDynamicSharedMemorySize,
                         SMEM_BYTES);
    coef_kernel<<<19, 256>>>(pos, val);
    apc_main<<<BATCH * H, 256, SMEM_BYTES>>>(x, out);
}